// round 11
// baseline (speedup 1.0000x reference)
#include <cuda_runtime.h>

// x1, x2: [N, D] fp32, N=8192, D=1024 row-major.
// ort = dot(colsum(x1), colsum(x2)) / (N*N)
//
// Single fused persistent-wave kernel:
//   Phase 1: 592 blocks (148 SMs x 4, one wave) compute partial colsums.
//   Arrival ticket via atomicAdd; last 128 arrivals become phase-2 workers
//   (R9-proven geometry: 2 float4-cols/block, one batched 5-row load burst).
//   Last worker writes the scalar and resets counters for the next replay.

static constexpr int D   = 1024;
static constexpr int D4  = D / 4;      // 256 float4 per row
static constexpr int NB  = 592;        // grid = one wave at 4 CTAs/SM
static constexpr int W   = 128;        // phase-2 worker blocks

// Scratch (__device__ globals; no allocation allowed)
__device__ float    g_part1[NB * D];   // 2.42 MB
__device__ float    g_part2[NB * D];   // 2.42 MB
__device__ double   g_acc  = 0.0;      // reset by finalizer each replay
__device__ unsigned g_bar  = 0;
__device__ unsigned g_done = 0;

__device__ __forceinline__ void acc4(float4& a, const float4 v) {
    a.x += v.x; a.y += v.y; a.z += v.z; a.w += v.w;
}

__global__ __launch_bounds__(256, 4) void ortho_fused(
    const float4* __restrict__ x1,
    const float4* __restrict__ x2,
    int nrows,
    float* __restrict__ out,
    double inv_count)
{
    const int t = threadIdx.x;
    const int b = blockIdx.x;

    // ── Phase 1: partial colsums. 4-row manual unroll -> 8 batched
    // independent LDG.128 (MLP=8); 2 accumulators break the FADD chain.
    {
        const size_t stride = (size_t)NB * D4;
        size_t off = (size_t)b * D4 + t;

        float4 a10 = make_float4(0.f,0.f,0.f,0.f), a11 = a10;
        float4 a20 = a10, a21 = a10;

        int r = b;
        for (; r + 3 * NB < nrows; r += 4 * NB, off += 4 * stride) {
            const float4 u0 = __ldg(x1 + off);
            const float4 u1 = __ldg(x1 + off +     stride);
            const float4 u2 = __ldg(x1 + off + 2 * stride);
            const float4 u3 = __ldg(x1 + off + 3 * stride);
            const float4 w0 = __ldg(x2 + off);
            const float4 w1 = __ldg(x2 + off +     stride);
            const float4 w2 = __ldg(x2 + off + 2 * stride);
            const float4 w3 = __ldg(x2 + off + 3 * stride);
            acc4(a10, u0); acc4(a11, u1); acc4(a10, u2); acc4(a11, u3);
            acc4(a20, w0); acc4(a21, w1); acc4(a20, w2); acc4(a21, w3);
        }
        for (; r < nrows; r += NB, off += stride) {
            acc4(a10, __ldg(x1 + off));
            acc4(a20, __ldg(x2 + off));
        }
        acc4(a10, a11);
        acc4(a20, a21);
        ((float4*)g_part1)[(size_t)b * D4 + t] = a10;
        ((float4*)g_part2)[(size_t)b * D4 + t] = a20;
    }

    // ── Arrival: publish partials, take a ticket.
    __threadfence();
    __syncthreads();
    __shared__ unsigned s_ticket;
    if (t == 0) s_ticket = atomicAdd(&g_bar, 1u);
    __syncthreads();
    const unsigned ticket = s_ticket;

    if (ticket < NB - W) return;          // early blocks exit, free SM slots
    const int g = (int)(ticket - (NB - W));   // worker id 0..127

    if (t == 0) {
        while (*(volatile unsigned*)&g_bar != NB) __nanosleep(32);
        __threadfence();                  // acquire: order partial reads
    }
    __syncthreads();

    // ── Phase 2 (R9 geometry): block g owns float4-cols {2g, 2g+1}.
    // col = t&1 (lane pairs read 32B contiguous), rl = t>>1 (128 row-lanes).
    // 592 = 4*128 + 80: 4 unconditional rows + 1 predicated, all loads batched.
    const int col = t & 1;
    const int rl  = t >> 1;               // 0..127
    const int cv  = g * 2 + col;

    const float4* __restrict__ p1 = (const float4*)g_part1;
    const float4* __restrict__ p2 = (const float4*)g_part2;

    const size_t st  = (size_t)128 * D4;
    const size_t off = (size_t)rl * D4 + cv;
    const bool tail  = (rl < NB - 512);   // rl < 80 -> 5th row exists
    const size_t off4 = tail ? (off + 4 * st) : off;

    const float4 u0 = p1[off];
    const float4 u1 = p1[off +     st];
    const float4 u2 = p1[off + 2 * st];
    const float4 u3 = p1[off + 3 * st];
    const float4 w0 = p2[off];
    const float4 w1 = p2[off +     st];
    const float4 w2 = p2[off + 2 * st];
    const float4 w3 = p2[off + 3 * st];
    float4 u4 = p1[off4];
    float4 w4 = p2[off4];
    if (!tail) { u4 = make_float4(0.f,0.f,0.f,0.f); w4 = u4; }

    float4 s1 = u0, s2 = w0;
    acc4(s1, u1); acc4(s1, u2); acc4(s1, u3); acc4(s1, u4);
    acc4(s2, w1); acc4(s2, w2); acc4(s2, w3); acc4(s2, w4);

    // warp reduce over rl (offsets 16..2 preserve col = lane&1)
    #pragma unroll
    for (int o = 16; o >= 2; o >>= 1) {
        s1.x += __shfl_down_sync(0xFFFFFFFFu, s1.x, o);
        s1.y += __shfl_down_sync(0xFFFFFFFFu, s1.y, o);
        s1.z += __shfl_down_sync(0xFFFFFFFFu, s1.z, o);
        s1.w += __shfl_down_sync(0xFFFFFFFFu, s1.w, o);
        s2.x += __shfl_down_sync(0xFFFFFFFFu, s2.x, o);
        s2.y += __shfl_down_sync(0xFFFFFFFFu, s2.y, o);
        s2.z += __shfl_down_sync(0xFFFFFFFFu, s2.z, o);
        s2.w += __shfl_down_sync(0xFFFFFFFFu, s2.w, o);
    }

    __shared__ float4 sh1[8][2], sh2[8][2];    // [warp][col]
    const int warp = t >> 5, lane = t & 31;
    if (lane < 2) { sh1[warp][lane] = s1; sh2[warp][lane] = s2; }
    __syncthreads();

    if (warp == 0 && lane < 16) {
        const int w = lane >> 1, c = lane & 1;
        float4 v1 = sh1[w][c], v2 = sh2[w][c];
        #pragma unroll
        for (int o = 8; o >= 2; o >>= 1) {
            v1.x += __shfl_down_sync(0x0000FFFFu, v1.x, o, 16);
            v1.y += __shfl_down_sync(0x0000FFFFu, v1.y, o, 16);
            v1.z += __shfl_down_sync(0x0000FFFFu, v1.z, o, 16);
            v1.w += __shfl_down_sync(0x0000FFFFu, v1.w, o, 16);
            v2.x += __shfl_down_sync(0x0000FFFFu, v2.x, o, 16);
            v2.y += __shfl_down_sync(0x0000FFFFu, v2.y, o, 16);
            v2.z += __shfl_down_sync(0x0000FFFFu, v2.z, o, 16);
            v2.w += __shfl_down_sync(0x0000FFFFu, v2.w, o, 16);
        }
        // lanes 0,1 hold COMPLETE colsums for cols 2g+{0,1} -> dot in double
        double d = (double)v1.x * (double)v2.x
                 + (double)v1.y * (double)v2.y
                 + (double)v1.z * (double)v2.z
                 + (double)v1.w * (double)v2.w;
        d += __shfl_down_sync(0x0000FFFFu, d, 1, 16);

        if (lane == 0) {
            atomicAdd(&g_acc, d);
            __threadfence();
            const unsigned dt = atomicAdd(&g_done, 1u);
            if (dt == W - 1) {
                out[0] = (float)(*(volatile double*)&g_acc * inv_count);
                g_acc  = 0.0;             // reset for next graph replay
                g_bar  = 0u;
                g_done = 0u;
            }
        }
    }
}

extern "C" void kernel_launch(void* const* d_in, const int* in_sizes, int n_in,
                              void* d_out, int out_size)
{
    const float4* x1 = (const float4*)d_in[0];
    const float4* x2 = (const float4*)d_in[1];
    float* out = (float*)d_out;

    const int rows1 = in_sizes[0] / D;   // 8192
    const int rows2 = in_sizes[1] / D;   // 8192
    const double inv_count = 1.0 / ((double)rows1 * (double)rows2);

    ortho_fused<<<NB, 256>>>(x1, x2, rows1, out, inv_count);
}